// round 3
// baseline (speedup 1.0000x reference)
#include <cuda_runtime.h>
#include <cstdint>

// Problem constants
#define BB      8192
#define DIN     64
#define DMID    1024
#define DOUT    64
#define KDOM    4

// Tiling
#define TM      128
#define TN      128
#define TK      16
#define PADDED  (BB + KDOM * TM)      // 8704: per-domain segments padded to TM
#define MTILES  (PADDED / TM)         // 68
#define NTILES  (DMID / TN)           // 8

// Scratch (device globals: no allocation allowed)
__device__ float g_bufA[PADDED * DMID];
__device__ float g_bufB[PADDED * DMID];
__device__ int   g_perm[PADDED];      // padded slot -> source row (-1 = padding)
__device__ int   g_seg[KDOM + 1];     // padded segment starts per domain
__device__ int   g_cnt[KDOM];

// ---------------------------------------------------------------------------
// Setup: histogram domains, compute tile-aligned segment offsets, init perm
// NOTE: domains is int32 on device (JAX x32 default downcasts the int64).
// ---------------------------------------------------------------------------
__global__ void setup_kernel(const int* __restrict__ domains) {
    __shared__ int cnt[KDOM];
    int t = threadIdx.x;
    if (t < KDOM) cnt[t] = 0;
    __syncthreads();
    for (int i = t; i < BB; i += blockDim.x) {
        int d = domains[i] & (KDOM - 1);   // clamp defensively
        atomicAdd(&cnt[d], 1);
    }
    for (int i = t; i < PADDED; i += blockDim.x)
        g_perm[i] = -1;
    __syncthreads();
    if (t == 0) {
        int off = 0;
        for (int d = 0; d < KDOM; d++) {
            g_seg[d] = off;
            g_cnt[d] = 0;
            off += (cnt[d] + TM - 1) / TM * TM;
        }
        g_seg[KDOM] = off;
    }
}

__global__ void build_perm_kernel(const int* __restrict__ domains) {
    int i = blockIdx.x * blockDim.x + threadIdx.x;
    if (i < BB) {
        int d = domains[i] & (KDOM - 1);
        int pos = g_seg[d] + atomicAdd(&g_cnt[d], 1);
        if (pos >= 0 && pos < PADDED)
            g_perm[pos] = i;
    }
}

// ---------------------------------------------------------------------------
// Main fused GEMM: C[TM x TN] = act(A[TM x Kdim] @ W[Kdim x DMID] + bias)
// GATHER=true: A rows come from X via g_perm (layer 1).
// Per-tile domain selects branch weights via wstride/bstride (0 => shared).
// ---------------------------------------------------------------------------
template<bool GATHER>
__global__ __launch_bounds__(256, 2)
void gemm128_kernel(const float* __restrict__ Xin, int a_sel,
                    const float* __restrict__ Wbase,
                    const float* __restrict__ bbase,
                    int c_sel, int Kdim,
                    long wstride, int bstride, int do_relu)
{
    __shared__ __align__(16) float As[2][TK][TM];
    __shared__ __align__(16) float Bs[2][TK][TN];

    const int m0  = blockIdx.y * TM;
    const int n0  = blockIdx.x * TN;
    const int tid = threadIdx.x;

    int dom = 0;
#pragma unroll
    for (int d = 1; d < KDOM; d++) if (m0 >= g_seg[d]) dom = d;
    const float* W    = Wbase + (long)dom * wstride;
    const float* bias = bbase + (long)dom * bstride;

    // A-tile loaders: 128 rows x 16 k, stored transposed [k][m]
    const int arow = tid & 127;
    const int akq  = tid >> 7;            // loads k-quads akq and akq+2
    // B-tile loaders: 16 k x 128 n
    const int brow = tid >> 5;            // rows brow, brow+8
    const int bn4  = tid & 31;            // float4 index in row

    const float* Arow;
    bool avalid = true;
    if (GATHER) {
        int s = g_perm[m0 + arow];
        avalid = (s >= 0);
        Arow = Xin + (long)(avalid ? s : 0) * Kdim;
    } else {
        const float* A = a_sel ? g_bufB : g_bufA;
        Arow = A + (long)(m0 + arow) * Kdim;
    }

    const int tx = tid & 15;
    const int ty = tid >> 4;

    float acc[8][8];
#pragma unroll
    for (int i = 0; i < 8; i++)
#pragma unroll
        for (int j = 0; j < 8; j++) acc[i][j] = 0.f;

    const int nkt = Kdim / TK;
    float4 apre[2], bpre[2];

    // preload k-tile 0
#pragma unroll
    for (int i = 0; i < 2; i++) {
        int kk = (akq + 2 * i) * 4;
        apre[i] = avalid ? *(const float4*)(Arow + kk) : make_float4(0.f, 0.f, 0.f, 0.f);
        int kr = brow + 8 * i;
        bpre[i] = *(const float4*)(W + (long)kr * DMID + n0 + bn4 * 4);
    }
#pragma unroll
    for (int i = 0; i < 2; i++) {
        int kk = (akq + 2 * i) * 4;
        As[0][kk + 0][arow] = apre[i].x;
        As[0][kk + 1][arow] = apre[i].y;
        As[0][kk + 2][arow] = apre[i].z;
        As[0][kk + 3][arow] = apre[i].w;
        *(((float4*)Bs[0][brow + 8 * i]) + bn4) = bpre[i];
    }
    __syncthreads();

    int buf = 0;
    for (int kt = 0; kt < nkt; kt++) {
        if (kt + 1 < nkt) {
            int kb = (kt + 1) * TK;
#pragma unroll
            for (int i = 0; i < 2; i++) {
                int kk = (akq + 2 * i) * 4;
                apre[i] = avalid ? *(const float4*)(Arow + kb + kk)
                                 : make_float4(0.f, 0.f, 0.f, 0.f);
                int kr = brow + 8 * i;
                bpre[i] = *(const float4*)(W + (long)(kb + kr) * DMID + n0 + bn4 * 4);
            }
        }
        // compute on buf
#pragma unroll
        for (int k = 0; k < TK; k++) {
            float4 a0 = *(const float4*)&As[buf][k][ty * 4];
            float4 a1 = *(const float4*)&As[buf][k][64 + ty * 4];
            float4 b0 = *(const float4*)&Bs[buf][k][tx * 4];
            float4 b1 = *(const float4*)&Bs[buf][k][64 + tx * 4];
            float a[8] = {a0.x, a0.y, a0.z, a0.w, a1.x, a1.y, a1.z, a1.w};
            float b[8] = {b0.x, b0.y, b0.z, b0.w, b1.x, b1.y, b1.z, b1.w};
#pragma unroll
            for (int i = 0; i < 8; i++)
#pragma unroll
                for (int j = 0; j < 8; j++)
                    acc[i][j] = fmaf(a[i], b[j], acc[i][j]);
        }
        if (kt + 1 < nkt) {
            int nb = buf ^ 1;
#pragma unroll
            for (int i = 0; i < 2; i++) {
                int kk = (akq + 2 * i) * 4;
                As[nb][kk + 0][arow] = apre[i].x;
                As[nb][kk + 1][arow] = apre[i].y;
                As[nb][kk + 2][arow] = apre[i].z;
                As[nb][kk + 3][arow] = apre[i].w;
                *(((float4*)Bs[nb][brow + 8 * i]) + bn4) = bpre[i];
            }
        }
        __syncthreads();
        buf ^= 1;
    }

    // epilogue: bias + optional ReLU
    float4 bias0 = *(const float4*)(bias + n0 + tx * 4);
    float4 bias1 = *(const float4*)(bias + n0 + 64 + tx * 4);
    float* Cb = c_sel ? g_bufB : g_bufA;
#pragma unroll
    for (int i = 0; i < 8; i++) {
        int row = m0 + ((i < 4) ? (ty * 4 + i) : (64 + ty * 4 + i - 4));
        float4 v0 = make_float4(acc[i][0] + bias0.x, acc[i][1] + bias0.y,
                                acc[i][2] + bias0.z, acc[i][3] + bias0.w);
        float4 v1 = make_float4(acc[i][4] + bias1.x, acc[i][5] + bias1.y,
                                acc[i][6] + bias1.z, acc[i][7] + bias1.w);
        if (do_relu) {
            v0.x = fmaxf(v0.x, 0.f); v0.y = fmaxf(v0.y, 0.f);
            v0.z = fmaxf(v0.z, 0.f); v0.w = fmaxf(v0.w, 0.f);
            v1.x = fmaxf(v1.x, 0.f); v1.y = fmaxf(v1.y, 0.f);
            v1.z = fmaxf(v1.z, 0.f); v1.w = fmaxf(v1.w, 0.f);
        }
        *(float4*)(Cb + (long)row * DMID + n0 + tx * 4) = v0;
        *(float4*)(Cb + (long)row * DMID + n0 + 64 + tx * 4) = v1;
    }
}

// ---------------------------------------------------------------------------
// Last layer: [TM x 1024] @ BW4[dom][1024 x 64] + Bb4[dom], scatter to output
// ---------------------------------------------------------------------------
__global__ __launch_bounds__(256, 2)
void gemm_last_kernel(int a_sel, const float* __restrict__ Wbase,
                      const float* __restrict__ bbase, float* __restrict__ out)
{
    __shared__ __align__(16) float As[2][TK][TM];
    __shared__ __align__(16) float Bs[2][TK][DOUT];

    const int m0  = blockIdx.x * TM;
    const int tid = threadIdx.x;

    int dom = 0;
#pragma unroll
    for (int d = 1; d < KDOM; d++) if (m0 >= g_seg[d]) dom = d;
    const float* W    = Wbase + (long)dom * (DMID * DOUT);
    const float* bias = bbase + (long)dom * DOUT;
    const float* A = a_sel ? g_bufB : g_bufA;

    const int arow = tid & 127;
    const int akq  = tid >> 7;
    const int bkr  = tid >> 4;   // 0..15 (k row)
    const int bn4  = tid & 15;   // float4 in row of 64
    const int tx   = tid & 15;
    const int ty   = tid >> 4;

    const float* Arow = A + (long)(m0 + arow) * DMID;

    float acc[8][4];
#pragma unroll
    for (int i = 0; i < 8; i++)
#pragma unroll
        for (int j = 0; j < 4; j++) acc[i][j] = 0.f;

    const int nkt = DMID / TK;   // 64
    float4 apre[2], bpre;

#pragma unroll
    for (int i = 0; i < 2; i++) {
        int kk = (akq + 2 * i) * 4;
        apre[i] = *(const float4*)(Arow + kk);
    }
    bpre = *(const float4*)(W + (long)bkr * DOUT + bn4 * 4);
#pragma unroll
    for (int i = 0; i < 2; i++) {
        int kk = (akq + 2 * i) * 4;
        As[0][kk + 0][arow] = apre[i].x;
        As[0][kk + 1][arow] = apre[i].y;
        As[0][kk + 2][arow] = apre[i].z;
        As[0][kk + 3][arow] = apre[i].w;
    }
    *(((float4*)Bs[0][bkr]) + bn4) = bpre;
    __syncthreads();

    int buf = 0;
    for (int kt = 0; kt < nkt; kt++) {
        if (kt + 1 < nkt) {
            int kb = (kt + 1) * TK;
#pragma unroll
            for (int i = 0; i < 2; i++) {
                int kk = (akq + 2 * i) * 4;
                apre[i] = *(const float4*)(Arow + kb + kk);
            }
            bpre = *(const float4*)(W + (long)(kb + bkr) * DOUT + bn4 * 4);
        }
#pragma unroll
        for (int k = 0; k < TK; k++) {
            float4 a0 = *(const float4*)&As[buf][k][ty * 4];
            float4 a1 = *(const float4*)&As[buf][k][64 + ty * 4];
            float4 b0 = *(const float4*)&Bs[buf][k][tx * 4];
            float a[8] = {a0.x, a0.y, a0.z, a0.w, a1.x, a1.y, a1.z, a1.w};
            float b[4] = {b0.x, b0.y, b0.z, b0.w};
#pragma unroll
            for (int i = 0; i < 8; i++)
#pragma unroll
                for (int j = 0; j < 4; j++)
                    acc[i][j] = fmaf(a[i], b[j], acc[i][j]);
        }
        if (kt + 1 < nkt) {
            int nb = buf ^ 1;
#pragma unroll
            for (int i = 0; i < 2; i++) {
                int kk = (akq + 2 * i) * 4;
                As[nb][kk + 0][arow] = apre[i].x;
                As[nb][kk + 1][arow] = apre[i].y;
                As[nb][kk + 2][arow] = apre[i].z;
                As[nb][kk + 3][arow] = apre[i].w;
            }
            *(((float4*)Bs[nb][bkr]) + bn4) = bpre;
        }
        __syncthreads();
        buf ^= 1;
    }

    // epilogue: bias (no relu), scatter back to original row order
    float4 bias0 = *(const float4*)(bias + tx * 4);
#pragma unroll
    for (int i = 0; i < 8; i++) {
        int row = m0 + ((i < 4) ? (ty * 4 + i) : (64 + ty * 4 + i - 4));
        int src = g_perm[row];
        if (src >= 0) {
            float4 v = make_float4(acc[i][0] + bias0.x, acc[i][1] + bias0.y,
                                   acc[i][2] + bias0.z, acc[i][3] + bias0.w);
            *(float4*)(out + (long)src * DOUT + tx * 4) = v;
        }
    }
}

// ---------------------------------------------------------------------------
extern "C" void kernel_launch(void* const* d_in, const int* in_sizes, int n_in,
                              void* d_out, int out_size)
{
    const float* X   = (const float*)d_in[0];
    const int*   dom = (const int*)d_in[1];      // int32 (JAX x32 default)
    const float *W1 = (const float*)d_in[2],  *b1  = (const float*)d_in[3];
    const float *W2 = (const float*)d_in[4],  *b2  = (const float*)d_in[5];
    const float *W3 = (const float*)d_in[6],  *b3  = (const float*)d_in[7];
    const float *W4 = (const float*)d_in[8],  *b4  = (const float*)d_in[9];
    const float *BW1 = (const float*)d_in[10], *Bb1 = (const float*)d_in[11];
    const float *BW2 = (const float*)d_in[12], *Bb2 = (const float*)d_in[13];
    const float *BW3 = (const float*)d_in[14], *Bb3 = (const float*)d_in[15];
    const float *BW4 = (const float*)d_in[16], *Bb4 = (const float*)d_in[17];
    float* out = (float*)d_out;

    const long WS = (long)DMID * DMID;   // per-domain weight stride (branch layers)

    setup_kernel<<<1, 1024>>>(dom);
    build_perm_kernel<<<(BB + 255) / 256, 256>>>(dom);

    dim3 grid(NTILES, MTILES);
    // layer 1: gather X -> bufA
    gemm128_kernel<true ><<<grid, 256>>>(X,       0, W1,  b1,  0, DIN,  0,  0,    1);
    // shared layers
    gemm128_kernel<false><<<grid, 256>>>(nullptr, 0, W2,  b2,  1, DMID, 0,  0,    1);
    gemm128_kernel<false><<<grid, 256>>>(nullptr, 1, W3,  b3,  0, DMID, 0,  0,    1);
    gemm128_kernel<false><<<grid, 256>>>(nullptr, 0, W4,  b4,  1, DMID, 0,  0,    1);
    // routed branch layers (per-tile domain via padded segments)
    gemm128_kernel<false><<<grid, 256>>>(nullptr, 1, BW1, Bb1, 0, DMID, WS, DMID, 1);
    gemm128_kernel<false><<<grid, 256>>>(nullptr, 0, BW2, Bb2, 1, DMID, WS, DMID, 1);
    gemm128_kernel<false><<<grid, 256>>>(nullptr, 1, BW3, Bb3, 0, DMID, WS, DMID, 1);
    // final layer + scatter
    gemm_last_kernel<<<MTILES, 256>>>(0, BW4, Bb4, out);
}

// round 5
// speedup vs baseline: 2.5421x; 2.5421x over previous
#include <cuda_runtime.h>
#include <cuda_bf16.h>
#include <cstdint>

#define BB     8192
#define DIN    64
#define DMID   1024
#define DOUT   64
#define KDOM   4
#define PADDED 9216
#define MT128  72
#define NPAIR  36
#define NKMID  16
#define TILE_E 8192
#define TILE_B 16384

// weight scratch elem offsets (bf16 elems, per plane)
#define OFF_W1  0L
#define OFF_W2  65536L
#define OFF_W3  1114112L
#define OFF_W4  2162688L
#define OFF_BW1 3211264L
#define OFF_BW2 7405568L
#define OFF_BW3 11599872L
#define OFF_BW4 15794176L
#define WTOT    16056320L

__device__ int g_perm[PADDED];
__device__ int g_seg[KDOM + 1];
__device__ int g_cnt[KDOM];

__device__ float4 g_wh4[WTOT / 8], g_wl4[WTOT / 8];
__device__ float4 g_xh4[73728],   g_xl4[73728];
__device__ float4 g_ah4[1179648], g_al4[1179648];
__device__ float4 g_bh4[1179648], g_bl4[1179648];

__device__ __forceinline__ uint32_t smem_u32(const void* p) {
    uint32_t a;
    asm("{ .reg .u64 t; cvta.to.shared.u64 t, %1; cvt.u32.u64 %0, t; }" : "=r"(a) : "l"(p));
    return a;
}
#define SW128(b) ((b) ^ (((b) >> 3) & 0x70))
#define CP16(s, g)  asm volatile("cp.async.cg.shared.global [%0], [%1], 16;" :: "r"(s), "l"(g))
#define CPCOMMIT()  asm volatile("cp.async.commit_group;" ::: "memory")
#define CPWAIT(n)   asm volatile("cp.async.wait_group %0;" :: "n"(n) : "memory")

#define LDSM4(r0,r1,r2,r3,a) \
    asm volatile("ldmatrix.sync.aligned.m8n8.x4.shared.b16 {%0,%1,%2,%3}, [%4];" \
        : "=r"(r0),"=r"(r1),"=r"(r2),"=r"(r3) : "r"(a))
#define LDSM2(r0,r1,a) \
    asm volatile("ldmatrix.sync.aligned.m8n8.x2.shared.b16 {%0,%1}, [%2];" \
        : "=r"(r0),"=r"(r1) : "r"(a))
#define MMA(d,a,b) \
    asm volatile("mma.sync.aligned.m16n8k16.row.col.f32.bf16.bf16.f32 " \
        "{%0,%1,%2,%3}, {%4,%5,%6,%7}, {%8,%9}, {%0,%1,%2,%3};" \
        : "+f"((d)[0]),"+f"((d)[1]),"+f"((d)[2]),"+f"((d)[3]) \
        : "r"((a)[0]),"r"((a)[1]),"r"((a)[2]),"r"((a)[3]),"r"((b)[0]),"r"((b)[1]))

__device__ __forceinline__ void split2(float x, uint16_t& h, uint16_t& l) {
    __nv_bfloat16 hb = __float2bfloat16(x);
    __nv_bfloat16 lb = __float2bfloat16(x - __bfloat162float(hb));
    h = __bfloat16_as_ushort(hb);
    l = __bfloat16_as_ushort(lb);
}

// ---------------------------------------------------------------- setup
__global__ void setup_kernel(const int* __restrict__ domains) {
    __shared__ int cnt[KDOM];
    int t = threadIdx.x;
    if (t < KDOM) cnt[t] = 0;
    __syncthreads();
    for (int i = t; i < BB; i += blockDim.x)
        atomicAdd(&cnt[domains[i] & (KDOM - 1)], 1);
    for (int i = t; i < PADDED; i += blockDim.x) g_perm[i] = -1;
    __syncthreads();
    if (t == 0) {
        int off = 0;
        for (int d = 0; d < KDOM; d++) {
            g_seg[d] = off; g_cnt[d] = 0;
            off += (cnt[d] + 255) / 256 * 256;
        }
        g_seg[KDOM] = off;
    }
}
__global__ void build_perm_kernel(const int* __restrict__ domains) {
    int i = blockIdx.x * blockDim.x + threadIdx.x;
    if (i < BB) {
        int d = domains[i] & (KDOM - 1);
        int pos = g_seg[d] + atomicAdd(&g_cnt[d], 1);
        if (pos >= 0 && pos < PADDED) g_perm[pos] = i;
    }
}

// ------------------------------------------------ X prep: gather+split+swizzle
__global__ void prep_x(const float* __restrict__ X) {
    __shared__ __align__(16) char sm[32768];
    int mt = blockIdx.x;
    for (int e = threadIdx.x; e < TILE_E; e += 256) {
        int r = e >> 6, c = e & 63;
        int s = g_perm[mt * 128 + r];
        float x = (s >= 0) ? X[(long)s * DIN + c] : 0.f;
        uint16_t h, l; split2(x, h, l);
        uint32_t off = SW128((uint32_t)(r * 128 + c * 2));
        *(uint16_t*)(sm + off)         = h;
        *(uint16_t*)(sm + 16384 + off) = l;
    }
    __syncthreads();
    const float4* s4 = (const float4*)sm;
    for (int i = threadIdx.x; i < 1024; i += 256) {
        g_xh4[mt * 1024 + i] = s4[i];
        g_xl4[mt * 1024 + i] = s4[1024 + i];
    }
}

// ------------------------------------------------ weight prep
struct WMeta { const float* src; long dst; int kch, N, TNt, shift; };
struct WArgs { WMeta m[20]; };
__global__ void prep_w(WArgs a) {
    WMeta w = a.m[blockIdx.y];
    int ntiles = w.N / w.TNt;
    int tile = blockIdx.x;
    if (tile >= w.kch * ntiles) return;
    int nt = tile / w.kch, kc = tile - nt * w.kch;
    __shared__ __align__(16) char sm[32768];
    int elems = w.TNt * 64;
    for (int e = threadIdx.x; e < elems; e += 256) {
        int n = e & (w.TNt - 1), k = e >> w.shift;
        float x = w.src[(long)(kc * 64 + k) * w.N + nt * w.TNt + n];
        uint16_t h, l; split2(x, h, l);
        uint32_t off = SW128((uint32_t)(n * 128 + k * 2));
        *(uint16_t*)(sm + off)             = h;
        *(uint16_t*)(sm + elems * 2 + off) = l;
    }
    __syncthreads();
    long delem = w.dst + (long)tile * elems;
    const float4* s4 = (const float4*)sm;
    float4* dh = (float4*)((__nv_bfloat16*)g_wh4 + delem);
    float4* dl = (float4*)((__nv_bfloat16*)g_wl4 + delem);
    int n4 = elems / 8;
    for (int i = threadIdx.x; i < n4; i += 256) {
        dh[i] = s4[i];
        dl[i] = s4[n4 + i];
    }
}

// ------------------------------------------------ mma.sync GEMM
// TM=256 (pair of 128-row tiles), TN = NTW*32, Kchunk=64, 512 threads.
// a_sel: 0=g_x, 1=g_a, 2=g_b ; c_sel: 1=g_a, 2=g_b (LAST writes fp32 out)
template<int NK, int NTW, bool LAST>
__global__ void __launch_bounds__(512, 1)
gemm_tc(int a_sel, long woff, long wstride, const float* __restrict__ bias,
        int bstride, int c_sel, float* __restrict__ out)
{
    constexpr int TN   = NTW * 32;
    constexpr int TNB  = TN * 128;          // B plane bytes
    constexpr int STGB = 65536 + 2 * TNB;   // stage bytes
    extern __shared__ char smem[];
    const uint32_t sb = smem_u32(smem);

    const int tid = threadIdx.x;
    const int lane = tid & 31, wid = tid >> 5;
    const int wm = wid & 3, wn = wid >> 2;
    const int ntile = LAST ? 0 : blockIdx.x;
    const int pair  = LAST ? blockIdx.x : blockIdx.y;
    const int m0 = pair * 256, n0 = ntile * TN;

    int dom = 0;
#pragma unroll
    for (int d = 1; d < KDOM; d++) if (m0 >= g_seg[d]) dom = d;
    const __nv_bfloat16* wh = (const __nv_bfloat16*)g_wh4 + woff + dom * wstride;
    const __nv_bfloat16* wl = (const __nv_bfloat16*)g_wl4 + woff + dom * wstride;
    const float* bptr = bias + (long)dom * bstride;

    const float4* Ah = (a_sel == 0) ? g_xh4 : (a_sel == 1) ? g_ah4 : g_bh4;
    const float4* Al = (a_sel == 0) ? g_xl4 : (a_sel == 1) ? g_al4 : g_bl4;
    char* Ch = (char*)((c_sel == 1) ? g_ah4 : g_bh4);
    char* Cl = (char*)((c_sel == 1) ? g_al4 : g_bl4);

    // per-thread ldmatrix addressing
    const int lane16 = lane & 15;
    const uint32_t axk = ((lane >> 4) & 1) << 4;
    uint32_t aoff[4], arx[4];
#pragma unroll
    for (int mt = 0; mt < 4; mt++) {
        int r = wm * 64 + mt * 16 + lane16;
        aoff[mt] = r * 128; arx[mt] = (r & 7) << 4;
    }
    const uint32_t bxk = ((lane >> 3) & 1) << 4;
    uint32_t boff[NTW], brx[NTW];
#pragma unroll
    for (int nt = 0; nt < NTW; nt++) {
        int r = wn * NTW * 8 + nt * 8 + (lane & 7);
        boff[nt] = r * 128; brx[nt] = (r & 7) << 4;
    }

    float acc[4][NTW][4];
#pragma unroll
    for (int mt = 0; mt < 4; mt++)
#pragma unroll
        for (int nt = 0; nt < NTW; nt++)
#pragma unroll
            for (int q = 0; q < 4; q++) acc[mt][nt][q] = 0.f;

    auto load_stage = [&](int st, int kc) {
        uint32_t s0 = sb + st * STGB;
#pragma unroll
        for (int m2 = 0; m2 < 2; m2++) {
            const float4* th = Ah + ((long)(2 * pair + m2) * NK + kc) * 1024;
            const float4* tl = Al + ((long)(2 * pair + m2) * NK + kc) * 1024;
#pragma unroll
            for (int i = 0; i < 2; i++) {
                int t = tid + i * 512;
                CP16(s0 + m2 * 16384 +          t * 16, th + t);
                CP16(s0 + m2 * 16384 + 32768 +  t * 16, tl + t);
            }
        }
        const float4* bh = (const float4*)(wh + ((long)ntile * NK + kc) * (long)(TN * 64));
        const float4* bl = (const float4*)(wl + ((long)ntile * NK + kc) * (long)(TN * 64));
#pragma unroll
        for (int i = 0; i < NTW / 2; i++) {
            int t = tid + i * 512;
            CP16(s0 + 65536 +        t * 16, bh + t);
            CP16(s0 + 65536 + TNB +  t * 16, bl + t);
        }
    };

    load_stage(0, 0); CPCOMMIT();
    if (NK > 1) { load_stage(1, 1); CPCOMMIT(); }

    for (int kc = 0; kc < NK; kc++) {
        if (kc + 1 < NK) { CPWAIT(1); } else { CPWAIT(0); }
        __syncthreads();
        const uint32_t sA  = sb + (kc & 1) * STGB;
        const uint32_t sBh = sA + 65536;
#pragma unroll
        for (int ks = 0; ks < 4; ks++) {
            const uint32_t cb = ks << 5;
            uint32_t bh[NTW][2], bl[NTW][2];
#pragma unroll
            for (int nt = 0; nt < NTW; nt++) {
                uint32_t ba = sBh + boff[nt] + ((cb | bxk) ^ brx[nt]);
                LDSM2(bh[nt][0], bh[nt][1], ba);
                LDSM2(bl[nt][0], bl[nt][1], ba + TNB);
            }
#pragma unroll
            for (int mt = 0; mt < 4; mt++) {
                uint32_t ah[4], al[4];
                uint32_t aa = sA + aoff[mt] + ((cb | axk) ^ arx[mt]);
                LDSM4(ah[0], ah[1], ah[2], ah[3], aa);
                LDSM4(al[0], al[1], al[2], al[3], aa + 32768);
#pragma unroll
                for (int nt = 0; nt < NTW; nt++) {
                    MMA(acc[mt][nt], ah, bh[nt]);
                    MMA(acc[mt][nt], ah, bl[nt]);
                    MMA(acc[mt][nt], al, bh[nt]);
                }
            }
        }
        if (kc + 2 < NK) {
            __syncthreads();
            load_stage(kc & 1, kc + 2); CPCOMMIT();
        }
    }

    // ---- epilogue
    const int rq = lane >> 2, cq = (lane & 3) * 2;
    if (!LAST) {
#pragma unroll
        for (int mt = 0; mt < 4; mt++) {
            int rA = wm * 64 + mt * 16 + rq;
#pragma unroll
            for (int nt = 0; nt < NTW; nt++) {
                int c = wn * NTW * 8 + nt * 8 + cq;
                float b0 = __ldg(bptr + n0 + c), b1 = __ldg(bptr + n0 + c + 1);
#pragma unroll
                for (int h = 0; h < 2; h++) {
                    int r = rA + h * 8;
                    float v0 = fmaxf(acc[mt][nt][h * 2 + 0] + b0, 0.f);
                    float v1 = fmaxf(acc[mt][nt][h * 2 + 1] + b1, 0.f);
                    uint16_t h0, l0, h1, l1;
                    split2(v0, h0, l0); split2(v1, h1, l1);
                    int gm = 2 * pair + (r >> 7), rl = r & 127, tt = c >> 6;
                    long tb = ((long)gm * NKMID + ntile * 2 + tt) * TILE_B;
                    uint32_t inrow = (uint32_t)((c & 63) * 2);
                    uint32_t phys = (uint32_t)(rl * 128) + (inrow ^ ((rl & 7) << 4));
                    *(uint32_t*)(Ch + tb + phys) = (uint32_t)h0 | ((uint32_t)h1 << 16);
                    *(uint32_t*)(Cl + tb + phys) = (uint32_t)l0 | ((uint32_t)l1 << 16);
                }
            }
        }
    } else {
#pragma unroll
        for (int mt = 0; mt < 4; mt++) {
            int rA = wm * 64 + mt * 16 + rq;
#pragma unroll
            for (int h = 0; h < 2; h++) {
                int r = rA + h * 8;
                int src = g_perm[m0 + r];
                if (src >= 0) {
#pragma unroll
                    for (int nt = 0; nt < NTW; nt++) {
                        int c = wn * NTW * 8 + nt * 8 + cq;
                        float2 v;
                        v.x = acc[mt][nt][h * 2 + 0] + __ldg(bptr + c);
                        v.y = acc[mt][nt][h * 2 + 1] + __ldg(bptr + c + 1);
                        *(float2*)(out + (long)src * DOUT + c) = v;
                    }
                }
            }
        }
    }
}

// ----------------------------------------------------------------
extern "C" void kernel_launch(void* const* d_in, const int* in_sizes, int n_in,
                              void* d_out, int out_size)
{
    const float* X   = (const float*)d_in[0];
    const int*   dom = (const int*)d_in[1];
    const float *W1 = (const float*)d_in[2],  *b1  = (const float*)d_in[3];
    const float *W2 = (const float*)d_in[4],  *b2  = (const float*)d_in[5];
    const float *W3 = (const float*)d_in[6],  *b3  = (const float*)d_in[7];
    const float *W4 = (const float*)d_in[8],  *b4  = (const float*)d_in[9];
    const float *BW1 = (const float*)d_in[10], *Bb1 = (const float*)d_in[11];
    const float *BW2 = (const float*)d_in[12], *Bb2 = (const float*)d_in[13];
    const float *BW3 = (const float*)d_in[14], *Bb3 = (const float*)d_in[15];
    const float *BW4 = (const float*)d_in[16], *Bb4 = (const float*)d_in[17];
    float* out = (float*)d_out;

    const int SM_MID = 2 * (65536 + 2 * 16384);   // 196608
    const int SM_LST = 2 * (65536 + 2 * 8192);    // 163840
    cudaFuncSetAttribute(gemm_tc<1, 4, false>,  cudaFuncAttributeMaxDynamicSharedMemorySize, SM_MID);
    cudaFuncSetAttribute(gemm_tc<16, 4, false>, cudaFuncAttributeMaxDynamicSharedMemorySize, SM_MID);
    cudaFuncSetAttribute(gemm_tc<16, 2, true>,  cudaFuncAttributeMaxDynamicSharedMemorySize, SM_LST);

    setup_kernel<<<1, 1024>>>(dom);
    build_perm_kernel<<<(BB + 255) / 256, 256>>>(dom);
    prep_x<<<MT128, 256>>>(X);

    WArgs wa;
    int idx = 0;
    wa.m[idx++] = {W1, OFF_W1, 1, DMID, 128, 7};
    wa.m[idx++] = {W2, OFF_W2, 16, DMID, 128, 7};
    wa.m[idx++] = {W3, OFF_W3, 16, DMID, 128, 7};
    wa.m[idx++] = {W4, OFF_W4, 16, DMID, 128, 7};
    for (int d = 0; d < 4; d++) wa.m[idx++] = {BW1 + (long)d*1048576, OFF_BW1 + (long)d*1048576, 16, DMID, 128, 7};
    for (int d = 0; d < 4; d++) wa.m[idx++] = {BW2 + (long)d*1048576, OFF_BW2 + (long)d*1048576, 16, DMID, 128, 7};
    for (int d = 0; d < 4; d++) wa.m[idx++] = {BW3 + (long)d*1048576, OFF_BW3 + (long)d*1048576, 16, DMID, 128, 7};
    for (int d = 0; d < 4; d++) wa.m[idx++] = {BW4 + (long)d*65536,   OFF_BW4 + (long)d*65536,   16, DOUT, 64, 6};
    prep_w<<<dim3(128, 20), 256>>>(wa);

    dim3 g(8, NPAIR);
    gemm_tc<1, 4, false> <<<g, 512, SM_MID>>>(0, OFF_W1, 0, b1, 0, 1, nullptr);
    gemm_tc<16, 4, false><<<g, 512, SM_MID>>>(1, OFF_W2, 0, b2, 0, 2, nullptr);
    gemm_tc<16, 4, false><<<g, 512, SM_MID>>>(2, OFF_W3, 0, b3, 0, 1, nullptr);
    gemm_tc<16, 4, false><<<g, 512, SM_MID>>>(1, OFF_W4, 0, b4, 0, 2, nullptr);
    gemm_tc<16, 4, false><<<g, 512, SM_MID>>>(2, OFF_BW1, 1048576L, Bb1, DMID, 1, nullptr);
    gemm_tc<16, 4, false><<<g, 512, SM_MID>>>(1, OFF_BW2, 1048576L, Bb2, DMID, 2, nullptr);
    gemm_tc<16, 4, false><<<g, 512, SM_MID>>>(2, OFF_BW3, 1048576L, Bb3, DMID, 1, nullptr);
    gemm_tc<16, 2, true> <<<NPAIR, 512, SM_LST>>>(1, OFF_BW4, 65536L, Bb4, 64, 0, out);
}

// round 6
// speedup vs baseline: 3.4292x; 1.3490x over previous
#include <cuda_runtime.h>
#include <cuda_fp16.h>
#include <cstdint>

#define BB     8192
#define DIN    64
#define DMID   1024
#define DOUT   64
#define KDOM   4
#define PADDED 9216
#define MT128  72
#define NPAIR  36
#define NKMID  16
#define TILE_E 8192
#define TILE_B 16384

// weight scratch elem offsets (fp16 elems, single plane)
#define OFF_W1  0L
#define OFF_W2  65536L
#define OFF_W3  1114112L
#define OFF_W4  2162688L
#define OFF_BW1 3211264L
#define OFF_BW2 7405568L
#define OFF_BW3 11599872L
#define OFF_BW4 15794176L
#define WTOT    16056320L

__device__ int g_perm[PADDED];
__device__ int g_seg[KDOM + 1];
__device__ int g_cnt[KDOM];

__device__ float4 g_w4[WTOT / 8];                    // weights, fp16 hi only
__device__ float4 g_xh4[73728],   g_xl4[73728];      // X split planes
__device__ float4 g_ah4[1179648], g_al4[1179648];    // activation ping
__device__ float4 g_bh4[1179648], g_bl4[1179648];    // activation pong

__device__ __forceinline__ uint32_t smem_u32(const void* p) {
    uint32_t a;
    asm("{ .reg .u64 t; cvta.to.shared.u64 t, %1; cvt.u32.u64 %0, t; }" : "=r"(a) : "l"(p));
    return a;
}
#define SW128(b) ((b) ^ (((b) >> 3) & 0x70))
#define CP16(s, g)  asm volatile("cp.async.cg.shared.global [%0], [%1], 16;" :: "r"(s), "l"(g))
#define CPCOMMIT()  asm volatile("cp.async.commit_group;" ::: "memory")
#define CPWAIT(n)   asm volatile("cp.async.wait_group %0;" :: "n"(n) : "memory")

#define LDSM4(r0,r1,r2,r3,a) \
    asm volatile("ldmatrix.sync.aligned.m8n8.x4.shared.b16 {%0,%1,%2,%3}, [%4];" \
        : "=r"(r0),"=r"(r1),"=r"(r2),"=r"(r3) : "r"(a))
#define LDSM2(r0,r1,a) \
    asm volatile("ldmatrix.sync.aligned.m8n8.x2.shared.b16 {%0,%1}, [%2];" \
        : "=r"(r0),"=r"(r1) : "r"(a))
#define MMA(d,a,b) \
    asm volatile("mma.sync.aligned.m16n8k16.row.col.f32.f16.f16.f32 " \
        "{%0,%1,%2,%3}, {%4,%5,%6,%7}, {%8,%9}, {%0,%1,%2,%3};" \
        : "+f"((d)[0]),"+f"((d)[1]),"+f"((d)[2]),"+f"((d)[3]) \
        : "r"((a)[0]),"r"((a)[1]),"r"((a)[2]),"r"((a)[3]),"r"((b)[0]),"r"((b)[1]))

__device__ __forceinline__ void split2h(float x, uint16_t& h, uint16_t& l) {
    __half hb = __float2half_rn(x);
    __half lb = __float2half_rn(x - __half2float(hb));
    h = __half_as_ushort(hb);
    l = __half_as_ushort(lb);
}

// ---------------------------------------------------------------- setup
__global__ void setup_kernel(const int* __restrict__ domains) {
    __shared__ int cnt[KDOM];
    int t = threadIdx.x;
    if (t < KDOM) cnt[t] = 0;
    __syncthreads();
    for (int i = t; i < BB; i += blockDim.x)
        atomicAdd(&cnt[domains[i] & (KDOM - 1)], 1);
    for (int i = t; i < PADDED; i += blockDim.x) g_perm[i] = -1;
    __syncthreads();
    if (t == 0) {
        int off = 0;
        for (int d = 0; d < KDOM; d++) {
            g_seg[d] = off; g_cnt[d] = 0;
            off += (cnt[d] + 255) / 256 * 256;
        }
        g_seg[KDOM] = off;
    }
}
__global__ void build_perm_kernel(const int* __restrict__ domains) {
    int i = blockIdx.x * blockDim.x + threadIdx.x;
    if (i < BB) {
        int d = domains[i] & (KDOM - 1);
        int pos = g_seg[d] + atomicAdd(&g_cnt[d], 1);
        if (pos >= 0 && pos < PADDED) g_perm[pos] = i;
    }
}

// ------------------------------------------------ X prep: gather+split+swizzle
__global__ void prep_x(const float* __restrict__ X) {
    __shared__ __align__(16) char sm[32768];
    int mt = blockIdx.x;
    for (int e = threadIdx.x; e < TILE_E; e += 256) {
        int r = e >> 6, c = e & 63;
        int s = g_perm[mt * 128 + r];
        float x = (s >= 0) ? X[(long)s * DIN + c] : 0.f;
        uint16_t h, l; split2h(x, h, l);
        uint32_t off = SW128((uint32_t)(r * 128 + c * 2));
        *(uint16_t*)(sm + off)         = h;
        *(uint16_t*)(sm + 16384 + off) = l;
    }
    __syncthreads();
    const float4* s4 = (const float4*)sm;
    for (int i = threadIdx.x; i < 1024; i += 256) {
        g_xh4[mt * 1024 + i] = s4[i];
        g_xl4[mt * 1024 + i] = s4[1024 + i];
    }
}

// ------------------------------------------------ weight prep (fp16 round, 1 plane)
struct WMeta { const float* src; long dst; int kch, N, TNt, shift; };
struct WArgs { WMeta m[20]; };
__global__ void prep_w(WArgs a) {
    WMeta w = a.m[blockIdx.y];
    int ntiles = w.N / w.TNt;
    int tile = blockIdx.x;
    if (tile >= w.kch * ntiles) return;
    int nt = tile / w.kch, kc = tile - nt * w.kch;
    __shared__ __align__(16) char sm[16384];
    int elems = w.TNt * 64;
    for (int e = threadIdx.x; e < elems; e += 256) {
        int n = e & (w.TNt - 1), k = e >> w.shift;
        float x = w.src[(long)(kc * 64 + k) * w.N + nt * w.TNt + n];
        uint32_t off = SW128((uint32_t)(n * 128 + k * 2));
        *(uint16_t*)(sm + off) = __half_as_ushort(__float2half_rn(x));
    }
    __syncthreads();
    long delem = w.dst + (long)tile * elems;
    const float4* s4 = (const float4*)sm;
    float4* dh = (float4*)((__half*)g_w4 + delem);
    int n4 = elems / 8;
    for (int i = threadIdx.x; i < n4; i += 256) dh[i] = s4[i];
}

// ------------------------------------------------ mma.sync GEMM
// TM=256 (pair of 128-row tiles), TN = NTW*32, Kchunk=64, 512 threads.
// A split fp16 hi/lo (2 planes), W single fp16 plane. 2 MMA terms.
template<int NK, int NTW, bool LAST>
__global__ void __launch_bounds__(512, 1)
gemm_tc(int a_sel, long woff, long wstride, const float* __restrict__ bias,
        int bstride, int c_sel, float* __restrict__ out)
{
    constexpr int TN   = NTW * 32;
    constexpr int TNB  = TN * 128;      // B plane bytes
    constexpr int STGB = 65536 + TNB;   // stage bytes (A 64K + B hi)
    extern __shared__ char smem[];
    const uint32_t sb = smem_u32(smem);

    const int tid = threadIdx.x;
    const int lane = tid & 31, wid = tid >> 5;
    const int wm = wid & 3, wn = wid >> 2;
    const int ntile = LAST ? 0 : blockIdx.x;
    const int pair  = LAST ? blockIdx.x : blockIdx.y;
    const int m0 = pair * 256, n0 = ntile * TN;

    int dom = 0;
#pragma unroll
    for (int d = 1; d < KDOM; d++) if (m0 >= g_seg[d]) dom = d;
    const __half* wp = (const __half*)g_w4 + woff + dom * wstride;
    const float* bptr = bias + (long)dom * bstride;

    const float4* Ah = (a_sel == 0) ? g_xh4 : (a_sel == 1) ? g_ah4 : g_bh4;
    const float4* Al = (a_sel == 0) ? g_xl4 : (a_sel == 1) ? g_al4 : g_bl4;
    char* Ch = (char*)((c_sel == 1) ? g_ah4 : g_bh4);
    char* Cl = (char*)((c_sel == 1) ? g_al4 : g_bl4);

    // per-thread ldmatrix addressing
    const int lane16 = lane & 15;
    const uint32_t axk = ((lane >> 4) & 1) << 4;
    uint32_t aoff[4], arx[4];
#pragma unroll
    for (int mt = 0; mt < 4; mt++) {
        int r = wm * 64 + mt * 16 + lane16;
        aoff[mt] = r * 128; arx[mt] = (r & 7) << 4;
    }
    const uint32_t bxk = ((lane >> 3) & 1) << 4;
    uint32_t boff[NTW], brx[NTW];
#pragma unroll
    for (int nt = 0; nt < NTW; nt++) {
        int r = wn * NTW * 8 + nt * 8 + (lane & 7);
        boff[nt] = r * 128; brx[nt] = (r & 7) << 4;
    }

    float acc[4][NTW][4];
#pragma unroll
    for (int mt = 0; mt < 4; mt++)
#pragma unroll
        for (int nt = 0; nt < NTW; nt++)
#pragma unroll
            for (int q = 0; q < 4; q++) acc[mt][nt][q] = 0.f;

    auto load_stage = [&](int st, int kc) {
        uint32_t s0 = sb + st * STGB;
#pragma unroll
        for (int m2 = 0; m2 < 2; m2++) {
            const float4* th = Ah + ((long)(2 * pair + m2) * NK + kc) * 1024;
            const float4* tl = Al + ((long)(2 * pair + m2) * NK + kc) * 1024;
#pragma unroll
            for (int i = 0; i < 2; i++) {
                int t = tid + i * 512;
                CP16(s0 + m2 * 16384 +          t * 16, th + t);
                CP16(s0 + m2 * 16384 + 32768 +  t * 16, tl + t);
            }
        }
        const float4* bh = (const float4*)(wp + ((long)ntile * NK + kc) * (long)(TN * 64));
#pragma unroll
        for (int i = 0; i < NTW / 2; i++) {
            int t = tid + i * 512;
            CP16(s0 + 65536 + t * 16, bh + t);
        }
    };

    load_stage(0, 0); CPCOMMIT();
    if (NK > 1) { load_stage(1, 1); CPCOMMIT(); }

    for (int kc = 0; kc < NK; kc++) {
        if (kc + 1 < NK) { CPWAIT(1); } else { CPWAIT(0); }
        __syncthreads();
        const uint32_t sA  = sb + (kc & 1) * STGB;
        const uint32_t sBh = sA + 65536;
#pragma unroll
        for (int ks = 0; ks < 4; ks++) {
            const uint32_t cb = ks << 5;
            uint32_t bh[NTW][2];
#pragma unroll
            for (int nt = 0; nt < NTW; nt++) {
                uint32_t ba = sBh + boff[nt] + ((cb | bxk) ^ brx[nt]);
                LDSM2(bh[nt][0], bh[nt][1], ba);
            }
#pragma unroll
            for (int mt = 0; mt < 4; mt++) {
                uint32_t ah[4], al[4];
                uint32_t aa = sA + aoff[mt] + ((cb | axk) ^ arx[mt]);
                LDSM4(ah[0], ah[1], ah[2], ah[3], aa);
                LDSM4(al[0], al[1], al[2], al[3], aa + 32768);
#pragma unroll
                for (int nt = 0; nt < NTW; nt++) {
                    MMA(acc[mt][nt], ah, bh[nt]);
                    MMA(acc[mt][nt], al, bh[nt]);
                }
            }
        }
        if (kc + 2 < NK) {
            __syncthreads();
            load_stage(kc & 1, kc + 2); CPCOMMIT();
        }
    }

    // ---- epilogue
    const int rq = lane >> 2, cq = (lane & 3) * 2;
    if (!LAST) {
#pragma unroll
        for (int mt = 0; mt < 4; mt++) {
            int rA = wm * 64 + mt * 16 + rq;
#pragma unroll
            for (int nt = 0; nt < NTW; nt++) {
                int c = wn * NTW * 8 + nt * 8 + cq;
                float b0 = __ldg(bptr + n0 + c), b1 = __ldg(bptr + n0 + c + 1);
#pragma unroll
                for (int h = 0; h < 2; h++) {
                    int r = rA + h * 8;
                    float v0 = fmaxf(acc[mt][nt][h * 2 + 0] + b0, 0.f);
                    float v1 = fmaxf(acc[mt][nt][h * 2 + 1] + b1, 0.f);
                    uint16_t h0, l0, h1, l1;
                    split2h(v0, h0, l0); split2h(v1, h1, l1);
                    int gm = 2 * pair + (r >> 7), rl = r & 127, tt = c >> 6;
                    long tb = ((long)gm * NKMID + ntile * 2 + tt) * TILE_B;
                    uint32_t inrow = (uint32_t)((c & 63) * 2);
                    uint32_t phys = (uint32_t)(rl * 128) + (inrow ^ ((rl & 7) << 4));
                    *(uint32_t*)(Ch + tb + phys) = (uint32_t)h0 | ((uint32_t)h1 << 16);
                    *(uint32_t*)(Cl + tb + phys) = (uint32_t)l0 | ((uint32_t)l1 << 16);
                }
            }
        }
    } else {
#pragma unroll
        for (int mt = 0; mt < 4; mt++) {
            int rA = wm * 64 + mt * 16 + rq;
#pragma unroll
            for (int h = 0; h < 2; h++) {
                int r = rA + h * 8;
                int src = g_perm[m0 + r];
                if (src >= 0) {
#pragma unroll
                    for (int nt = 0; nt < NTW; nt++) {
                        int c = wn * NTW * 8 + nt * 8 + cq;
                        float2 v;
                        v.x = acc[mt][nt][h * 2 + 0] + __ldg(bptr + c);
                        v.y = acc[mt][nt][h * 2 + 1] + __ldg(bptr + c + 1);
                        *(float2*)(out + (long)src * DOUT + c) = v;
                    }
                }
            }
        }
    }
}

// ----------------------------------------------------------------
extern "C" void kernel_launch(void* const* d_in, const int* in_sizes, int n_in,
                              void* d_out, int out_size)
{
    const float* X   = (const float*)d_in[0];
    const int*   dom = (const int*)d_in[1];
    const float *W1 = (const float*)d_in[2],  *b1  = (const float*)d_in[3];
    const float *W2 = (const float*)d_in[4],  *b2  = (const float*)d_in[5];
    const float *W3 = (const float*)d_in[6],  *b3  = (const float*)d_in[7];
    const float *W4 = (const float*)d_in[8],  *b4  = (const float*)d_in[9];
    const float *BW1 = (const float*)d_in[10], *Bb1 = (const float*)d_in[11];
    const float *BW2 = (const float*)d_in[12], *Bb2 = (const float*)d_in[13];
    const float *BW3 = (const float*)d_in[14], *Bb3 = (const float*)d_in[15];
    const float *BW4 = (const float*)d_in[16], *Bb4 = (const float*)d_in[17];
    float* out = (float*)d_out;

    const int SM_MID = 2 * (65536 + 16384);   // 163840
    const int SM_LST = 2 * (65536 + 8192);    // 147456
    cudaFuncSetAttribute(gemm_tc<1, 4, false>,  cudaFuncAttributeMaxDynamicSharedMemorySize, SM_MID);
    cudaFuncSetAttribute(gemm_tc<16, 4, false>, cudaFuncAttributeMaxDynamicSharedMemorySize, SM_MID);
    cudaFuncSetAttribute(gemm_tc<16, 2, true>,  cudaFuncAttributeMaxDynamicSharedMemorySize, SM_LST);

    setup_kernel<<<1, 1024>>>(dom);
    build_perm_kernel<<<(BB + 255) / 256, 256>>>(dom);
    prep_x<<<MT128, 256>>>(X);

    WArgs wa;
    int idx = 0;
    wa.m[idx++] = {W1, OFF_W1, 1, DMID, 128, 7};
    wa.m[idx++] = {W2, OFF_W2, 16, DMID, 128, 7};
    wa.m[idx++] = {W3, OFF_W3, 16, DMID, 128, 7};
    wa.m[idx++] = {W4, OFF_W4, 16, DMID, 128, 7};
    for (int d = 0; d < 4; d++) wa.m[idx++] = {BW1 + (long)d*1048576, OFF_BW1 + (long)d*1048576, 16, DMID, 128, 7};
    for (int d = 0; d < 4; d++) wa.m[idx++] = {BW2 + (long)d*1048576, OFF_BW2 + (long)d*1048576, 16, DMID, 128, 7};
    for (int d = 0; d < 4; d++) wa.m[idx++] = {BW3 + (long)d*1048576, OFF_BW3 + (long)d*1048576, 16, DMID, 128, 7};
    for (int d = 0; d < 4; d++) wa.m[idx++] = {BW4 + (long)d*65536,   OFF_BW4 + (long)d*65536,   16, DOUT, 64, 6};
    prep_w<<<dim3(128, 20), 256>>>(wa);

    dim3 g(8, NPAIR);
    gemm_tc<1, 4, false> <<<g, 512, SM_MID>>>(0, OFF_W1, 0, b1, 0, 1, nullptr);
    gemm_tc<16, 4, false><<<g, 512, SM_MID>>>(1, OFF_W2, 0, b2, 0, 2, nullptr);
    gemm_tc<16, 4, false><<<g, 512, SM_MID>>>(2, OFF_W3, 0, b3, 0, 1, nullptr);
    gemm_tc<16, 4, false><<<g, 512, SM_MID>>>(1, OFF_W4, 0, b4, 0, 2, nullptr);
    gemm_tc<16, 4, false><<<g, 512, SM_MID>>>(2, OFF_BW1, 1048576L, Bb1, DMID, 1, nullptr);
    gemm_tc<16, 4, false><<<g, 512, SM_MID>>>(1, OFF_BW2, 1048576L, Bb2, DMID, 2, nullptr);
    gemm_tc<16, 4, false><<<g, 512, SM_MID>>>(2, OFF_BW3, 1048576L, Bb3, DMID, 1, nullptr);
    gemm_tc<16, 2, true> <<<NPAIR, 512, SM_LST>>>(1, OFF_BW4, 65536L, Bb4, 64, 0, out);
}